// round 9
// baseline (speedup 1.0000x reference)
#include <cuda_runtime.h>

// Problem constants
#define B_      64
#define NM_     32
#define NS_     32
#define K_      3
#define HID_    64
#define NLAYER_ 4
#define S_      2048     // B*NS
#define P_      6        // K!
#define NTHR_   512      // 16 warps

// itertools.permutations(range(3)); allperm[k][p] = c_perm[p][k]
__constant__ int c_perm[6][3] = {
    {0,1,2},{0,2,1},{1,0,2},{1,2,0},{2,0,1},{2,1,0}
};

// per-subgraph post-set2 vectors (S, 64) — logical dim order
__device__ float g_subg[S_ * HID_];

// ---- shared memory layout (floats) ----
// H stored PHYSICALLY INTERLEAVED: phys q holds logical d=(q>>1)+(q&1)*32,
// so lane L's ull at phys {2L,2L+1} = logical dims {L, L+32}.
#define OFF_A    0                       // A2 pair-transposed adj (512 ull = 1024 f)
#define OFF_HA   1024                    // H ping                 (12288)
#define OFF_HB   (OFF_HA + 12288)        // H pong                 (12288)
#define OFF_WB0  (OFF_HB + 12288)        // weight buffer 0        (8448)
#define OFF_WB1  (OFF_WB0 + 8448)        // weight buffer 1        (8448)
#define OFF_TS   (OFF_WB1 + 8448)        // per-warp staging 16x768 (12288)
#define OFF_SS   (OFF_TS + 12288)        // node-sum vector        (64)
#define SMEM_FLOATS (OFF_SS + 64)
#define SMEM_BYTES  (SMEM_FLOATS * 4)    // 219,392 B

// offsets inside a weight buffer
// Layer buffers: W1/W2 in "W4" packed layout: W4[k2*128 + 4*q + c] =
//   W[(2*k2 + (c>>1))][q + (c&1)*32]   (logical indices)
// Set-MLP buffer (epilogue): OLD dlog-permuted layout (epilogue code unchanged).
// Biases/gamma/beta: plain logical order.
#define WOFF_W1  0
#define WOFF_W2  4096
#define WOFF_B1  8192
#define WOFF_B2  8256
#define WOFF_G   8320
#define WOFF_BE  8384

typedef unsigned long long ull;

__device__ __forceinline__ void ffma2(ull& d, ull a, ull b) {
    asm("fma.rn.f32x2 %0, %1, %2, %0;" : "+l"(d) : "l"(a), "l"(b));
}
__device__ __forceinline__ ull fma2g(ull a, ull b, ull c) {
    ull r;
    asm("fma.rn.f32x2 %0, %1, %2, %3;" : "=l"(r) : "l"(a), "l"(b), "l"(c));
    return r;
}
__device__ __forceinline__ ull add2(ull a, ull b) {
    ull r;
    asm("add.rn.f32x2 %0, %1, %2;" : "=l"(r) : "l"(a), "l"(b));
    return r;
}
__device__ __forceinline__ ull mul2(ull a, ull b) {
    ull r;
    asm("mul.rn.f32x2 %0, %1, %2;" : "=l"(r) : "l"(a), "l"(b));
    return r;
}
__device__ __forceinline__ ull splat2(float v) {
    ull r;
    asm("mov.b64 %0, {%1, %1};" : "=l"(r) : "f"(v));
    return r;
}
__device__ __forceinline__ ull pack2f(float lo, float hi) {
    ull r;
    asm("mov.b64 %0, {%1, %2};" : "=l"(r) : "f"(lo), "f"(hi));
    return r;
}
__device__ __forceinline__ float2 unpk(ull v) {
    float2 f;
    asm("mov.b64 {%0, %1}, %2;" : "=f"(f.x), "=f"(f.y) : "l"(v));
    return f;
}
__device__ __forceinline__ void lds_v2u64(ull& a, ull& b, unsigned addr) {
    asm("ld.shared.v2.u64 {%0, %1}, [%2];" : "=l"(a), "=l"(b) : "r"(addr));
}
__device__ __forceinline__ int dlog(int q) { return (q >> 1) + ((q & 1) << 5); }

// layer weights: W4 packed layout + plain biases/gamma/beta
__device__ __forceinline__ void load_layer_weights_w4(
    float* dst, int tid,
    const float* __restrict__ W1g, const float* __restrict__ b1g,
    const float* __restrict__ W2g, const float* __restrict__ b2g,
    const float* __restrict__ gg,  const float* __restrict__ beg, int l)
{
    const float* w1 = W1g + l * 4096;
    const float* w2 = W2g + l * 4096;
    for (int idx = tid; idx < 4096; idx += NTHR_) {
        int k2 = idx >> 7, r = idx & 127, q = r >> 2, c = r & 3;
        int src = (2 * k2 + (c >> 1)) * 64 + q + ((c & 1) << 5);
        dst[WOFF_W1 + idx] = w1[src];
        dst[WOFF_W2 + idx] = w2[src];
    }
    if (tid < 64) {
        dst[WOFF_B1 + tid] = b1g[l * 64 + tid];
        dst[WOFF_B2 + tid] = b2g[l * 64 + tid];
        dst[WOFF_G  + tid] = gg [l * 64 + tid];
        dst[WOFF_BE + tid] = beg[l * 64 + tid];
    }
}

// row-pair MLP: out[r][d] = b[d] + sum_k t[r][k] * W[k][d]
// t pairs in warp staging (ull Tst[pr*64 + k], k logical), W in W4 layout.
__device__ __forceinline__ void mlp_rowpair(
    ull* a0, ull* a1, unsigned twsh, const float* Wmat,
    int lane, float blo, float bhi)
{
    ull b0 = splat2(blo), b1 = splat2(bhi);
    #pragma unroll
    for (int pr = 0; pr < 6; pr++) { a0[pr] = b0; a1[pr] = b1; }
    #pragma unroll 8
    for (int k2 = 0; k2 < 32; k2++) {
        float4 w4 = *(const float4*)&Wmat[k2 * 128 + 4 * lane];
        ull se0 = splat2(w4.x), se1 = splat2(w4.y);
        ull so0 = splat2(w4.z), so1 = splat2(w4.w);
        #pragma unroll
        for (int pr = 0; pr < 6; pr++) {
            ull te, to;
            lds_v2u64(te, to, twsh + (unsigned)(pr * 512 + k2 * 16));
            ffma2(a0[pr], se0, te); ffma2(a1[pr], se1, te);
            ffma2(a0[pr], so0, to); ffma2(a1[pr], so1, to);
        }
    }
}

__global__ void __launch_bounds__(NTHR_, 1) idmpnn_main(
    const int*   __restrict__ x,        // (B, NM, 1)
    const float* __restrict__ subadj,   // (B, NM, NM)
    const int*   __restrict__ subgs,    // (S, K)
    const int*   __restrict__ num_node, // (B,)
    const float* __restrict__ idemb,    // (5, 64)
    const float* __restrict__ node_emb, // (101, 64)
    const float* __restrict__ W1g, const float* __restrict__ b1g,
    const float* __restrict__ W2g, const float* __restrict__ b2g,
    const float* __restrict__ gg,  const float* __restrict__ beg,
    const float* __restrict__ s1W, const float* __restrict__ s1b,
    const float* __restrict__ s2W, const float* __restrict__ s2b)
{
    extern __shared__ float sm[];
    const int s    = blockIdx.x;
    const int b    = s >> 5;            // graph id (NS=32)
    const int tid  = threadIdx.x;
    const int warp = tid >> 5;
    const int lane = tid & 31;
    const int l2   = 2 * lane;          // physical base of this lane's pair

    const unsigned smsh = (unsigned)__cvta_generic_to_shared(sm);
    const unsigned a2sh = smsh + OFF_A * 4;
    const unsigned twsh = smsh + (OFF_TS + warp * 768) * 4;
    ull* TwU = (ull*)(sm + OFF_TS + warp * 768);

    // ---- A2: pair-transposed adjacency: A2[j*16+ip] = {A[2ip][j], A[2ip+1][j]} ----
    {
        ull* A2 = (ull*)(sm + OFF_A);
        for (int e = tid; e < 512; e += NTHR_) {
            int j = e >> 4, ip = e & 15;
            float lo = subadj[b * 1024 + (2 * ip) * 32 + j];
            float hi = subadj[b * 1024 + (2 * ip + 1) * 32 + j];
            A2[e] = pack2f(lo, hi);
        }
    }
    // ---- layer-0 weights ----
    load_layer_weights_w4(sm + OFF_WB0, tid, W1g, b1g, W2g, b2g, gg, beg, 0);

    // ---- initial H (physical-interleaved dims) ----
    {
        const int sg0 = subgs[3 * s + 0];
        const int sg1 = subgs[3 * s + 1];
        const int sg2 = subgs[3 * s + 2];
        for (int e = tid; e < 12288; e += NTHR_) {
            int row  = e >> 6;          // row = node*6 + p
            int q    = e & 63;
            int node = row / 6;
            int p    = row - node * 6;
            int d    = dlog(q);
            float v = node_emb[x[b * 32 + node] * 64 + d];
            int k = (node == sg0) ? 0 : (node == sg1) ? 1 : (node == sg2) ? 2 : -1;
            if (k >= 0) v *= idemb[c_perm[p][k] * 64 + d];
            sm[OFF_HA + e] = v;
        }
    }
    __syncthreads();

    // this warp's 12 rows = 3 tasks x 4 rows = 6 row-pairs
    const int t0 = warp * 3;
    int rowg[12], pArr[3], ip2[3];
    #pragma unroll
    for (int q = 0; q < 3; q++) {
        int t = t0 + q;
        int p = t >> 3;
        int i0 = (t & 7) * 4;
        pArr[q] = p;
        ip2[q]  = (t & 7) * 2;          // A2 pair index of rows (i0, i0+1)
        #pragma unroll
        for (int r = 0; r < 4; r++)
            rowg[q * 4 + r] = (i0 + r) * 6 + p;
    }
    const bool unip = (pArr[0] == pArr[2]);

    int srcO = OFF_HA, dstO = OFF_HB;

    // ================= layer loop =================
    for (int l = 0; l < NLAYER_; l++) {
        const float* W = sm + ((l & 1) ? OFF_WB1 : OFF_WB0);
        float* Wnext = sm + (((l + 1) & 1) ? OFF_WB1 : OFF_WB0);

        if (l < NLAYER_ - 1) {
            load_layer_weights_w4(Wnext, tid, W1g, b1g, W2g, b2g, gg, beg, l + 1);
        } else {
            // set-MLP weights for the epilogue — OLD dlog-permuted layout
            for (int idx = tid; idx < 4096; idx += NTHR_) {
                int kq = idx >> 6, q = idx & 63;
                int src = dlog(kq) * 64 + dlog(q);
                Wnext[WOFF_W1 + idx] = s1W[src];
                Wnext[WOFF_W2 + idx] = s2W[src];
            }
            if (tid < 64) {
                Wnext[WOFF_B1 + tid] = s1b[dlog(tid)];
                Wnext[WOFF_B2 + tid] = s2b[dlog(tid)];
            }
        }

        const float* src = sm + srcO;
        float*       dst = sm + dstO;

        // ---- phase A: m = A @ H, packed over row-pairs ----
        ull a0[6], a1[6];
        #pragma unroll
        for (int pr = 0; pr < 6; pr++) { a0[pr] = 0ull; a1[pr] = 0ull; }

        if (unip) {
            const int p0 = pArr[0];
            #pragma unroll 8
            for (int j = 0; j < 32; j++) {
                ull hp = *(const ull*)&src[(j * 6 + p0) * 64 + l2];
                float2 hf = unpk(hp);
                ull s0 = splat2(hf.x), s1 = splat2(hf.y);
                #pragma unroll
                for (int q = 0; q < 3; q++) {
                    ull pe, po;
                    lds_v2u64(pe, po, a2sh + (unsigned)((j * 16 + ip2[q]) * 8));
                    ffma2(a0[2*q],   s0, pe); ffma2(a1[2*q],   s1, pe);
                    ffma2(a0[2*q+1], s0, po); ffma2(a1[2*q+1], s1, po);
                }
            }
        } else {
            #pragma unroll 8
            for (int j = 0; j < 32; j++) {
                #pragma unroll
                for (int q = 0; q < 3; q++) {
                    ull hp = *(const ull*)&src[(j * 6 + pArr[q]) * 64 + l2];
                    float2 hf = unpk(hp);
                    ull s0 = splat2(hf.x), s1 = splat2(hf.y);
                    ull pe, po;
                    lds_v2u64(pe, po, a2sh + (unsigned)((j * 16 + ip2[q]) * 8));
                    ffma2(a0[2*q],   s0, pe); ffma2(a1[2*q],   s1, pe);
                    ffma2(a0[2*q+1], s0, po); ffma2(a1[2*q+1], s1, po);
                }
            }
        }
        // stage m pairs: Tst[pr*64 + k] (k logical; lane stores k=L and k=L+32)
        #pragma unroll
        for (int pr = 0; pr < 6; pr++) {
            TwU[pr * 64 + lane]      = a0[pr];
            TwU[pr * 64 + lane + 32] = a1[pr];
        }
        __syncwarp();

        // ---- MLP layer 1 ----
        mlp_rowpair(a0, a1, twsh, W + WOFF_W1, lane,
                    W[WOFF_B1 + lane], W[WOFF_B1 + lane + 32]);
        __syncwarp();
        // relu + restage
        #pragma unroll
        for (int pr = 0; pr < 6; pr++) {
            float2 f0 = unpk(a0[pr]);
            float2 f1 = unpk(a1[pr]);
            TwU[pr * 64 + lane]      = pack2f(fmaxf(f0.x, 0.f), fmaxf(f0.y, 0.f));
            TwU[pr * 64 + lane + 32] = pack2f(fmaxf(f1.x, 0.f), fmaxf(f1.y, 0.f));
        }
        __syncwarp();

        // ---- MLP layer 2 ----
        mlp_rowpair(a0, a1, twsh, W + WOFF_W2, lane,
                    W[WOFF_B2 + lane], W[WOFF_B2 + lane + 32]);

        // ---- LayerNorm + relu + residual (packed over row-pairs) ----
        {
            ull sa[6];
            #pragma unroll
            for (int pr = 0; pr < 6; pr++) sa[pr] = add2(a0[pr], a1[pr]);
            #pragma unroll
            for (int o = 16; o; o >>= 1) {
                #pragma unroll
                for (int pr = 0; pr < 6; pr++)
                    sa[pr] = add2(sa[pr], __shfl_xor_sync(0xffffffffu, sa[pr], o));
            }
            const ull neginv = splat2(-1.f / 64.f);
            #pragma unroll
            for (int pr = 0; pr < 6; pr++) {
                ull nm = mul2(sa[pr], neginv);
                a0[pr] = add2(a0[pr], nm);
                a1[pr] = add2(a1[pr], nm);
            }
            ull v[6];
            #pragma unroll
            for (int pr = 0; pr < 6; pr++)
                v[pr] = add2(mul2(a0[pr], a0[pr]), mul2(a1[pr], a1[pr]));
            #pragma unroll
            for (int o = 16; o; o >>= 1) {
                #pragma unroll
                for (int pr = 0; pr < 6; pr++)
                    v[pr] = add2(v[pr], __shfl_xor_sync(0xffffffffu, v[pr], o));
            }
            ull g0  = splat2(W[WOFF_G  + lane]), g1  = splat2(W[WOFF_G  + lane + 32]);
            ull be0 = splat2(W[WOFF_BE + lane]), be1 = splat2(W[WOFF_BE + lane + 32]);
            #pragma unroll
            for (int pr = 0; pr < 6; pr++) {
                float2 vf = unpk(v[pr]);
                float rs0 = rsqrtf(vf.x * (1.f / 64.f) + 1e-5f);
                float rs1 = rsqrtf(vf.y * (1.f / 64.f) + 1e-5f);
                ull rp = pack2f(rs0, rs1);
                ull o0 = fma2g(mul2(a0[pr], rp), g0, be0);  // dims d0, rows {r0,r1}
                ull o1 = fma2g(mul2(a1[pr], rp), g1, be1);  // dims d1
                float2 f0 = unpk(o0), f1 = unpk(o1);
                // repack row-major: row r0 gets {d0,d1} = {f0.x, f1.x}
                ull w0 = pack2f(fmaxf(f0.x, 0.f), fmaxf(f1.x, 0.f));
                ull w1 = pack2f(fmaxf(f0.y, 0.f), fmaxf(f1.y, 0.f));
                int r0g = rowg[2 * pr], r1g = rowg[2 * pr + 1];
                w0 = add2(w0, *(const ull*)&src[r0g * 64 + l2]);
                w1 = add2(w1, *(const ull*)&src[r1g * 64 + l2]);
                *(ull*)&dst[r0g * 64 + l2] = w0;
                *(ull*)&dst[r1g * 64 + l2] = w1;
            }
        }
        __syncthreads();
        int tmp = srcO; srcO = dstO; dstO = tmp;
    }
    // final H in HA; set weights (old permuted layout) in WB0

    const float* Wset = sm + OFF_WB0;

    // zero padded-node rows
    {
        const int nn = num_node[b];
        for (int e = nn * 384 + tid; e < 12288; e += NTHR_) sm[OFF_HA + e] = 0.f;
    }
    __syncthreads();

    // mean over perms -> HB (physical layout preserved)
    for (int e = tid; e < 2048; e += NTHR_) {
        int i = e >> 6, q = e & 63;
        float acc = 0.f;
        #pragma unroll
        for (int p = 0; p < 6; p++) acc += sm[OFF_HA + i * 384 + p * 64 + q];
        sm[OFF_HB + e] = acc * (1.f / 6.f);
    }
    __syncthreads();

    // set1 MLP over 32 node rows (2 per warp) + node-sum partials  (old mapping)
    {
        const int r0 = warp * 2;
        ull a[2] = {0ull, 0ull};
        #pragma unroll
        for (int k = 0; k < 64; k += 4) {
            float4 mv[2];
            #pragma unroll
            for (int r = 0; r < 2; r++)
                mv[r] = *(const float4*)&sm[OFF_HB + (r0 + r) * 64 + k];
            #pragma unroll
            for (int kk = 0; kk < 4; kk++) {
                ull wp = *(const ull*)&Wset[WOFF_W1 + (k + kk) * 64 + l2];
                ffma2(a[0], splat2(((const float*)&mv[0])[kk]), wp);
                ffma2(a[1], splat2(((const float*)&mv[1])[kk]), wp);
            }
        }
        float2 b1p = *(const float2*)&Wset[WOFF_B1 + l2];
        float p0 = 0.f, p1 = 0.f;
        #pragma unroll
        for (int r = 0; r < 2; r++) {
            float2 v = unpk(a[r]);
            p0 += fmaxf(v.x + b1p.x, 0.f);
            p1 += fmaxf(v.y + b1p.y, 0.f);
        }
        sm[OFF_TS + warp * 64 + l2]     = p0;
        sm[OFF_TS + warp * 64 + l2 + 1] = p1;
    }
    __syncthreads();
    if (tid < 64) {
        float ss = 0.f;
        #pragma unroll
        for (int w = 0; w < 16; w++) ss += sm[OFF_TS + w * 64 + tid];
        sm[OFF_SS + tid] = ss;   // physical order
    }
    __syncthreads();

    // set2 MLP on summed vector -> per-subgraph output (logical order to g_subg)
    if (warp == 0) {
        float a0s = 0.f, a1s = 0.f;
        #pragma unroll
        for (int q = 0; q < 64; q++) {
            float v = sm[OFF_SS + q];
            a0s += v * Wset[WOFF_W2 + q * 64 + l2];
            a1s += v * Wset[WOFF_W2 + q * 64 + l2 + 1];
        }
        float2 b2p = *(const float2*)&Wset[WOFF_B2 + l2];
        g_subg[s * 64 + lane]      = fmaxf(a0s + b2p.x, 0.f);
        g_subg[s * 64 + lane + 32] = fmaxf(a1s + b2p.y, 0.f);
    }
}

__global__ void __launch_bounds__(64, 1) finalize_k(
    const float* __restrict__ outW, const float* __restrict__ outb,
    float* __restrict__ out)
{
    const int b = blockIdx.x;
    const int d = threadIdx.x;
    float m = g_subg[(b * 32) * 64 + d];
    #pragma unroll
    for (int ss = 1; ss < 32; ss++)
        m = fmaxf(m, g_subg[(b * 32 + ss) * 64 + d]);
    float v = m * outW[d];
    #pragma unroll
    for (int o = 16; o; o >>= 1) v += __shfl_xor_sync(0xffffffffu, v, o);
    __shared__ float red[2];
    if ((d & 31) == 0) red[d >> 5] = v;
    __syncthreads();
    if (d == 0) out[b] = red[0] + red[1] + outb[0];
}

extern "C" void kernel_launch(void* const* d_in, const int* in_sizes, int n_in,
                              void* d_out, int out_size)
{
    const int*   x        = (const int*)  d_in[0];
    const float* subadj   = (const float*)d_in[1];
    const int*   subgs    = (const int*)  d_in[2];
    const int*   num_node = (const int*)  d_in[3];
    // d_in[4] = num_subg (unused)
    const float* idemb    = (const float*)d_in[5];
    const float* node_emb = (const float*)d_in[6];
    const float* W1       = (const float*)d_in[7];
    const float* b1       = (const float*)d_in[8];
    const float* W2       = (const float*)d_in[9];
    const float* b2       = (const float*)d_in[10];
    const float* g        = (const float*)d_in[11];
    const float* be       = (const float*)d_in[12];
    const float* s1W      = (const float*)d_in[13];
    const float* s1b      = (const float*)d_in[14];
    const float* s2W      = (const float*)d_in[15];
    const float* s2b      = (const float*)d_in[16];
    const float* outW     = (const float*)d_in[17];
    const float* outb     = (const float*)d_in[18];

    cudaFuncSetAttribute(idmpnn_main,
                         cudaFuncAttributeMaxDynamicSharedMemorySize, SMEM_BYTES);

    idmpnn_main<<<S_, NTHR_, SMEM_BYTES>>>(
        x, subadj, subgs, num_node, idemb, node_emb,
        W1, b1, W2, b2, g, be, s1W, s1b, s2W, s2b);
    finalize_k<<<B_, 64>>>(outW, outb, (float*)d_out);
}